// round 1
// baseline (speedup 1.0000x reference)
#include <cuda_runtime.h>
#include <math.h>
#include <stdint.h>

// ---------------- problem constants ----------------
#define T_STEPS 16
#define BATCH   4096
#define FDIM    64
#define BN      81920          // BATCH * 20 nodes
#define NE      327680
#define MD1     1280
#define MD2     640
#define MD3     320

// ---------------- scratch (device globals; no allocation allowed) ----------------
__device__ float g_T1x[(size_t)BN * FDIM];
__device__ float g_T2x[(size_t)BN * FDIM];
__device__ float g_T1h[(size_t)BN * FDIM];
__device__ float g_T2h[(size_t)BN * FDIM];
__device__ float g_Hst[(size_t)BN * FDIM];
__device__ float g_Zg [(size_t)BN * FDIM];
__device__ float g_HR [(size_t)BN * FDIM];
__device__ float g_pre[(size_t)BN * FDIM];
__device__ float g_deg [BN];
__device__ float g_dinv[BN];
__device__ int   g_cnt [BN];
__device__ int   g_rowptr[BN + 1];
__device__ int   g_next[BN];
__device__ int   g_csr_src[NE];
__device__ float g_csr_w [NE];
__device__ float g_y1[(size_t)BATCH * MD2];
__device__ float g_y2[(size_t)BATCH * MD3];

// ---------------- setup kernels ----------------
__global__ void k_init() {
    size_t i = (size_t)blockIdx.x * blockDim.x + threadIdx.x;  // exactly BN*FDIM threads
    g_Hst[i] = 0.0f;
    if (i < BN) { g_deg[i] = 0.0f; g_cnt[i] = 0; }
}

__global__ void k_degcnt(const int* __restrict__ ei, const float* __restrict__ ew) {
    int e = blockIdx.x * blockDim.x + threadIdx.x;
    if (e < NE) {
        atomicAdd(&g_deg[ei[e]], ew[e]);       // deg = segment_sum(w, src)
        atomicAdd(&g_cnt[ei[NE + e]], 1);      // in-degree by dst
    }
}

__global__ void k_dinv() {
    int i = blockIdx.x * blockDim.x + threadIdx.x;
    if (i < BN) { float d = g_deg[i]; g_dinv[i] = (d > 0.0f) ? rsqrtf(d) : 0.0f; }
}

// one-block exclusive scan of g_cnt -> g_rowptr / g_next (BN = 80 * 1024)
__global__ void k_scan() {
    __shared__ int s[1024];
    __shared__ int sh_carry;
    int tid = threadIdx.x;
    if (tid == 0) sh_carry = 0;
    __syncthreads();
    for (int c = 0; c < BN / 1024; c++) {
        int i = c * 1024 + tid;
        int v = g_cnt[i];
        int x = v;
        s[tid] = x; __syncthreads();
        for (int off = 1; off < 1024; off <<= 1) {
            int t = (tid >= off) ? s[tid - off] : 0;
            __syncthreads();
            x += t; s[tid] = x; __syncthreads();
        }
        int carry = sh_carry;
        int rp = carry + x - v;
        g_rowptr[i] = rp; g_next[i] = rp;
        __syncthreads();
        if (tid == 1023) sh_carry = carry + x;
        __syncthreads();
    }
    if (tid == 0) g_rowptr[BN] = sh_carry;
}

__global__ void k_fill(const int* __restrict__ ei, const float* __restrict__ ew) {
    int e = blockIdx.x * blockDim.x + threadIdx.x;
    if (e < NE) {
        int s = ei[e], d = ei[NE + e];
        int pos = atomicAdd(&g_next[d], 1);
        g_csr_src[pos] = s;
        g_csr_w[pos] = -g_dinv[s] * ew[e] * g_dinv[d];   // scaled-Laplacian edge weight
    }
}

// ---------------- SpMM: warp per dst-row, gather via CSR (optionally dual matrix) ----------------
// pass1: out = L*in.   pass2 (sub != null): out = 2*L*in - sub
__global__ void k_spmm(const float* __restrict__ in0, const float* __restrict__ in1,
                       float* __restrict__ out0, float* __restrict__ out1,
                       const float* __restrict__ sub0, const float* __restrict__ sub1) {
    int w    = (blockIdx.x * blockDim.x + threadIdx.x) >> 5;   // one row per warp
    int lane = threadIdx.x & 31;
    if (w >= BN) return;
    int beg = g_rowptr[w], end = g_rowptr[w + 1];
    float2 a0 = make_float2(0.f, 0.f), a1 = make_float2(0.f, 0.f);
    const float2* p0 = (const float2*)in0;
    if (in1) {
        const float2* p1 = (const float2*)in1;
        for (int e = beg; e < end; e++) {
            int s = g_csr_src[e]; float wt = g_csr_w[e];
            float2 v0 = p0[(size_t)s * 32 + lane];
            float2 v1 = p1[(size_t)s * 32 + lane];
            a0.x = fmaf(wt, v0.x, a0.x); a0.y = fmaf(wt, v0.y, a0.y);
            a1.x = fmaf(wt, v1.x, a1.x); a1.y = fmaf(wt, v1.y, a1.y);
        }
    } else {
        for (int e = beg; e < end; e++) {
            int s = g_csr_src[e]; float wt = g_csr_w[e];
            float2 v0 = p0[(size_t)s * 32 + lane];
            a0.x = fmaf(wt, v0.x, a0.x); a0.y = fmaf(wt, v0.y, a0.y);
        }
    }
    size_t o = (size_t)w * 32 + lane;
    if (sub0) { float2 sv = ((const float2*)sub0)[o]; a0.x = 2.f*a0.x - sv.x; a0.y = 2.f*a0.y - sv.y; }
    ((float2*)out0)[o] = a0;
    if (in1 && out1) {
        if (sub1) { float2 sv = ((const float2*)sub1)[o]; a1.x = 2.f*a1.x - sv.x; a1.y = 2.f*a1.y - sv.y; }
        ((float2*)out1)[o] = a1;
    }
}

// ---------------- fused GEMM (FFMA2 packed fp32) with GRU/MLP epilogues ----------------
// A is either "termed" (up to 6 sources of BN x 64, selected by k/64) or contiguous (lda).
// B row k comes from B0 (first 192 rows) or B1 (rows 192..383) when termed; contiguous ldb otherwise.
struct GemmTerms { const float* t[6]; };

#define MODE_Z    0   // out = sigmoid(acc + b0 + b1)
#define MODE_RHR  1   // out = H * sigmoid(acc + b0 + b1)                (aux0 = H)
#define MODE_PRE  2   // out = acc + b0 + b1
#define MODE_G2   3   // Ht = tanh(acc + pre); H = relu(Z*H + (1-Z)*Ht)  (aux0=pre, aux1=Z, aux2=H)
#define MODE_RELU 4   // out = relu(acc + b0)

union U2 { unsigned long long u; float2 f; };

__global__ __launch_bounds__(256)
void k_gemm(GemmTerms A, const float* Acont, int lda,
            const float* B0, const float* B1, int ldb, int Ktot,
            const float* bias0, const float* bias1,
            float* out, int ldc, int mode,
            const float* aux0, const float* aux1, const float* aux2) {
    const int row0 = blockIdx.x * 128;
    const int col0 = blockIdx.y * 64;
    __shared__ __align__(16) float  As[16][128];   // A^T tile: As[k][r]
    __shared__ __align__(16) float2 Bs[16][64];    // B tile, value duplicated in both halves

    int tid = threadIdx.x;
    int tx = tid & 15;       // 4 consecutive output cols
    int ty = tid >> 4;       // 8 output rows (4 packed pairs)

    U2 acc[4][4];
#pragma unroll
    for (int i = 0; i < 4; i++)
#pragma unroll
        for (int j = 0; j < 4; j++) acc[i][j].u = 0ull;

    for (int kb = 0; kb < Ktot; kb += 16) {
        // load A tile (128 rows x 16 k), store transposed
#pragma unroll
        for (int i = 0; i < 2; i++) {
            int idx = tid + i * 256;
            int r = idx >> 2, q = idx & 3;
            const float* ap;
            if (Acont) ap = Acont + (size_t)(row0 + r) * lda + kb + q * 4;
            else       ap = A.t[kb >> 6] + (size_t)(row0 + r) * 64 + (kb & 63) + q * 4;
            float4 v = *(const float4*)ap;
            As[q * 4 + 0][r] = v.x; As[q * 4 + 1][r] = v.y;
            As[q * 4 + 2][r] = v.z; As[q * 4 + 3][r] = v.w;
        }
        // load B tile (16 k x 64 cols), duplicate values for f32x2
        {
            int kr = tid >> 4, cq = tid & 15;
            int krow = kb + kr;
            const float* brow = (B1 && krow >= 192) ? (B1 + (size_t)(krow - 192) * ldb)
                                                    : (B0 + (size_t)krow * ldb);
            float4 v = *(const float4*)(brow + col0 + cq * 4);
            Bs[kr][cq * 4 + 0] = make_float2(v.x, v.x);
            Bs[kr][cq * 4 + 1] = make_float2(v.y, v.y);
            Bs[kr][cq * 4 + 2] = make_float2(v.z, v.z);
            Bs[kr][cq * 4 + 3] = make_float2(v.w, v.w);
        }
        __syncthreads();
#pragma unroll
        for (int k = 0; k < 16; k++) {
            unsigned long long a[4], b[4];
#pragma unroll
            for (int rp = 0; rp < 4; rp++)
                a[rp] = *(const unsigned long long*)&As[k][ty * 8 + rp * 2];
#pragma unroll
            for (int c = 0; c < 4; c++)
                b[c] = *(const unsigned long long*)&Bs[k][tx * 4 + c];
#pragma unroll
            for (int rp = 0; rp < 4; rp++)
#pragma unroll
                for (int c = 0; c < 4; c++)
                    asm("fma.rn.f32x2 %0, %1, %2, %0;"
                        : "+l"(acc[rp][c].u) : "l"(a[rp]), "l"(b[c]));
        }
        __syncthreads();
    }

    // epilogue
#pragma unroll
    for (int rp = 0; rp < 4; rp++) {
#pragma unroll
        for (int c = 0; c < 4; c++) {
            float2 v = acc[rp][c].f;
            int col = col0 + tx * 4 + c;
            float bb = 0.0f;
            if (bias0) bb += bias0[col];
            if (bias1) bb += bias1[col];
#pragma unroll
            for (int h = 0; h < 2; h++) {
                int row = row0 + ty * 8 + rp * 2 + h;
                float x = (h ? v.y : v.x) + bb;
                size_t oidx = (size_t)row * ldc + col;
                if (mode == MODE_Z) {
                    out[oidx] = 1.0f / (1.0f + expf(-x));
                } else if (mode == MODE_RHR) {
                    float r = 1.0f / (1.0f + expf(-x));
                    out[oidx] = aux0[oidx] * r;
                } else if (mode == MODE_PRE) {
                    out[oidx] = x;
                } else if (mode == MODE_G2) {
                    float ht = tanhf(x + aux0[oidx]);
                    float z  = aux1[oidx];
                    float h0 = aux2[oidx];
                    float hn = z * h0 + (1.0f - z) * ht;
                    out[oidx] = fmaxf(hn, 0.0f);
                } else { // MODE_RELU
                    out[oidx] = fmaxf(x, 0.0f);
                }
            }
        }
    }
}

// ---------------- head: logits (320 -> 2) + softmax, warp per row ----------------
__global__ void k_head(const float* __restrict__ y2, const float* __restrict__ W3,
                       const float* __restrict__ b3, float* __restrict__ out) {
    int w    = (blockIdx.x * blockDim.x + threadIdx.x) >> 5;
    int lane = threadIdx.x & 31;
    if (w >= BATCH) return;
    float p0 = 0.f, p1 = 0.f;
    for (int i = lane; i < MD3; i += 32) {
        float v = y2[(size_t)w * MD3 + i];
        p0 = fmaf(v, W3[i * 2 + 0], p0);
        p1 = fmaf(v, W3[i * 2 + 1], p1);
    }
#pragma unroll
    for (int o = 16; o; o >>= 1) {
        p0 += __shfl_xor_sync(0xffffffffu, p0, o);
        p1 += __shfl_xor_sync(0xffffffffu, p1, o);
    }
    if (lane == 0) {
        float l0 = p0 + b3[0], l1 = p1 + b3[1];
        float m = fmaxf(l0, l1);
        float e0 = expf(l0 - m), e1 = expf(l1 - m);
        float s = e0 + e1;
        out[(size_t)w * 2 + 0] = e0 / s;
        out[(size_t)w * 2 + 1] = e1 / s;
    }
}

// ---------------- host orchestration ----------------
extern "C" void kernel_launch(void* const* d_in, const int* in_sizes, int n_in,
                              void* d_out, int out_size) {
    const float* x_temporal = (const float*)d_in[0];
    const int*   edge_index = (const int*)d_in[1];
    const float* edge_w     = (const float*)d_in[2];
    const float* W_xz = (const float*)d_in[3];  const float* b_xz = (const float*)d_in[4];
    const float* W_hz = (const float*)d_in[5];  const float* b_hz = (const float*)d_in[6];
    const float* W_xr = (const float*)d_in[7];  const float* b_xr = (const float*)d_in[8];
    const float* W_hr = (const float*)d_in[9];  const float* b_hr = (const float*)d_in[10];
    const float* W_xh = (const float*)d_in[11]; const float* b_xh = (const float*)d_in[12];
    const float* W_hh = (const float*)d_in[13]; const float* b_hh = (const float*)d_in[14];
    const float* W1 = (const float*)d_in[15];   const float* b1 = (const float*)d_in[16];
    const float* W2 = (const float*)d_in[17];   const float* b2 = (const float*)d_in[18];
    const float* W3 = (const float*)d_in[19];   const float* b3 = (const float*)d_in[20];
    float* out = (float*)d_out;

    float *T1x, *T2x, *T1h, *T2h, *H, *Z, *HR, *PRE, *y1, *y2;
    cudaGetSymbolAddress((void**)&T1x, g_T1x);
    cudaGetSymbolAddress((void**)&T2x, g_T2x);
    cudaGetSymbolAddress((void**)&T1h, g_T1h);
    cudaGetSymbolAddress((void**)&T2h, g_T2h);
    cudaGetSymbolAddress((void**)&H,   g_Hst);
    cudaGetSymbolAddress((void**)&Z,   g_Zg);
    cudaGetSymbolAddress((void**)&HR,  g_HR);
    cudaGetSymbolAddress((void**)&PRE, g_pre);
    cudaGetSymbolAddress((void**)&y1,  g_y1);
    cudaGetSymbolAddress((void**)&y2,  g_y2);

    // graph preprocessing (every call: deterministic, replay-safe)
    k_init  <<<(BN * FDIM) / 256, 256>>>();
    k_degcnt<<<NE / 256, 256>>>(edge_index, edge_w);
    k_dinv  <<<BN / 256, 256>>>();
    k_scan  <<<1, 1024>>>();
    k_fill  <<<NE / 256, 256>>>(edge_index, edge_w);

    const int spmm_blocks = BN / 8;  // warp per row, 8 warps per block

    for (int t = 0; t < T_STEPS; t++) {
        const float* X = x_temporal + (size_t)t * BN * FDIM;

        // Chebyshev terms for X and H branches
        k_spmm<<<spmm_blocks, 256>>>(X,   H,   T1x, T1h, nullptr, nullptr);
        k_spmm<<<spmm_blocks, 256>>>(T1x, T1h, T2x, T2h, X, H);

        GemmTerms A6; A6.t[0] = X; A6.t[1] = T1x; A6.t[2] = T2x;
                      A6.t[3] = H; A6.t[4] = T1h; A6.t[5] = T2h;
        // Z gate
        k_gemm<<<dim3(BN / 128, 1), 256>>>(A6, nullptr, 0, W_xz, W_hz, 64, 384,
                                           b_xz, b_hz, Z, 64, MODE_Z,
                                           nullptr, nullptr, nullptr);
        // R gate fused with HR = H * R
        k_gemm<<<dim3(BN / 128, 1), 256>>>(A6, nullptr, 0, W_xr, W_hr, 64, 384,
                                           b_xr, b_hr, HR, 64, MODE_RHR,
                                           H, nullptr, nullptr);
        // candidate X-branch pre-activation (+ both candidate biases)
        GemmTerms A3; A3.t[0] = X; A3.t[1] = T1x; A3.t[2] = T2x;
                      A3.t[3] = nullptr; A3.t[4] = nullptr; A3.t[5] = nullptr;
        k_gemm<<<dim3(BN / 128, 1), 256>>>(A3, nullptr, 0, W_xh, nullptr, 64, 192,
                                           b_xh, b_hh, PRE, 64, MODE_PRE,
                                           nullptr, nullptr, nullptr);

        // Chebyshev terms for HR branch (reuse T1x/T2x buffers)
        k_spmm<<<spmm_blocks, 256>>>(HR,  nullptr, T1x, nullptr, nullptr, nullptr);
        k_spmm<<<spmm_blocks, 256>>>(T1x, nullptr, T2x, nullptr, HR, nullptr);

        // candidate H-branch GEMM fused with full GRU update (writes H in place)
        GemmTerms A3r; A3r.t[0] = HR; A3r.t[1] = T1x; A3r.t[2] = T2x;
                       A3r.t[3] = nullptr; A3r.t[4] = nullptr; A3r.t[5] = nullptr;
        k_gemm<<<dim3(BN / 128, 1), 256>>>(A3r, nullptr, 0, W_hh, nullptr, 64, 192,
                                           nullptr, nullptr, H, 64, MODE_G2,
                                           PRE, Z, H);
    }

    // MLP head: H viewed as [4096 x 1280]
    GemmTerms dummy; for (int i = 0; i < 6; i++) dummy.t[i] = nullptr;
    k_gemm<<<dim3(BATCH / 128, MD2 / 64), 256>>>(dummy, H, MD1, W1, nullptr, MD2, MD1,
                                                 b1, nullptr, y1, MD2, MODE_RELU,
                                                 nullptr, nullptr, nullptr);
    k_gemm<<<dim3(BATCH / 128, MD3 / 64), 256>>>(dummy, y1, MD2, W2, nullptr, MD3, MD2,
                                                 b2, nullptr, y2, MD3, MODE_RELU,
                                                 nullptr, nullptr, nullptr);
    k_head<<<BATCH / 8, 256>>>(y2, W3, b3, out);
}

// round 6
// speedup vs baseline: 1.1364x; 1.1364x over previous
#include <cuda_runtime.h>
#include <math.h>
#include <stdint.h>

// ---------------- problem constants ----------------
#define T_STEPS 16
#define BATCH   4096
#define FDIM    64
#define BN      81920          // BATCH * 20 nodes
#define NE      327680
#define MD1     1280
#define MD2     640
#define MD3     320

// ---------------- scratch (device globals; no allocation allowed) ----------------
__device__ float g_T1x[(size_t)BN * FDIM];
__device__ float g_T2x[(size_t)BN * FDIM];
__device__ float g_T1h[(size_t)BN * FDIM];
__device__ float g_T2h[(size_t)BN * FDIM];
__device__ float g_Hst[(size_t)BN * FDIM];
__device__ float g_Zg [(size_t)BN * FDIM];
__device__ float g_HR [(size_t)BN * FDIM];
__device__ float g_pre[(size_t)BN * FDIM];
__device__ float g_deg [BN];
__device__ float g_dinv[BN];
__device__ int   g_cnt [BN];
__device__ int   g_rowptr[BN + 1];
__device__ int   g_next[BN];
__device__ int2  g_csr[NE];          // (src, weight-as-int) packed: one 8B load per edge
__device__ int   g_bsum[80];
__device__ int   g_boff[80];
__device__ float g_y1[(size_t)BATCH * MD2];
__device__ float g_y2[(size_t)BATCH * MD3];

// ---------------- accurate activations (the R0-passing versions) ----------------
__device__ __forceinline__ float fsigmoid(float x) {
    return 1.0f / (1.0f + expf(-x));
}

// ---------------- setup kernels ----------------
__global__ void k_init() {
    size_t i = (size_t)blockIdx.x * blockDim.x + threadIdx.x;  // exactly BN*FDIM threads
    g_Hst[i] = 0.0f;
    if (i < BN) { g_deg[i] = 0.0f; g_cnt[i] = 0; }
}

__global__ void k_degcnt(const int* __restrict__ ei, const float* __restrict__ ew) {
    int e = blockIdx.x * blockDim.x + threadIdx.x;
    if (e < NE) {
        atomicAdd(&g_deg[ei[e]], ew[e]);       // deg = segment_sum(w, src)
        atomicAdd(&g_cnt[ei[NE + e]], 1);      // in-degree by dst
    }
}

__global__ void k_dinv() {
    int i = blockIdx.x * blockDim.x + threadIdx.x;
    if (i < BN) { float d = g_deg[i]; g_dinv[i] = (d > 0.0f) ? rsqrtf(d) : 0.0f; }
}

// 3-phase parallel exclusive scan of g_cnt (BN = 80 * 1024)
__global__ void k_scan1() {            // 80 blocks x 1024: local scan + block sums
    __shared__ int s[1024];
    int tid = threadIdx.x;
    int i = blockIdx.x * 1024 + tid;
    int v = g_cnt[i];
    int x = v;
    s[tid] = x; __syncthreads();
    for (int o = 1; o < 1024; o <<= 1) {
        int t = (tid >= o) ? s[tid - o] : 0;
        __syncthreads();
        x += t; s[tid] = x; __syncthreads();
    }
    g_rowptr[i] = x - v;               // local exclusive
    if (tid == 1023) g_bsum[blockIdx.x] = x;
}
__global__ void k_scan2() {            // 1 block x 128: scan the 80 block sums
    __shared__ int s[128];
    int tid = threadIdx.x;
    int v = (tid < 80) ? g_bsum[tid] : 0;
    int x = v;
    s[tid] = x; __syncthreads();
    for (int o = 1; o < 128; o <<= 1) {
        int t = (tid >= o) ? s[tid - o] : 0;
        __syncthreads();
        x += t; s[tid] = x; __syncthreads();
    }
    if (tid < 80) g_boff[tid] = x - v;
}
__global__ void k_scan3() {            // 80 blocks x 1024: add offsets
    int tid = threadIdx.x;
    int i = blockIdx.x * 1024 + tid;
    int rp = g_rowptr[i] + g_boff[blockIdx.x];
    g_rowptr[i] = rp;
    g_next[i] = rp;
    if (i == 0) g_rowptr[BN] = NE;
}

__global__ void k_fill(const int* __restrict__ ei, const float* __restrict__ ew) {
    int e = blockIdx.x * blockDim.x + threadIdx.x;
    if (e < NE) {
        int s = ei[e], d = ei[NE + e];
        int pos = atomicAdd(&g_next[d], 1);
        float w = -g_dinv[s] * ew[e] * g_dinv[d];   // scaled-Laplacian edge weight
        g_csr[pos] = make_int2(s, __float_as_int(w));
    }
}

// ---------------- SpMM: warp per dst-row, gather via CSR (optionally dual matrix) ----------------
// pass1: out = L*in.   pass2 (sub != null): out = 2*L*in - sub
__global__ void k_spmm(const float* __restrict__ in0, const float* __restrict__ in1,
                       float* __restrict__ out0, float* __restrict__ out1,
                       const float* __restrict__ sub0, const float* __restrict__ sub1) {
    int w    = (blockIdx.x * blockDim.x + threadIdx.x) >> 5;   // one row per warp
    int lane = threadIdx.x & 31;
    if (w >= BN) return;
    int beg = g_rowptr[w], end = g_rowptr[w + 1];
    float2 a0 = make_float2(0.f, 0.f), a1 = make_float2(0.f, 0.f);
    const float2* p0 = (const float2*)in0;
    if (in1) {
        const float2* p1 = (const float2*)in1;
        for (int e = beg; e < end; e++) {
            int2 ed = g_csr[e];
            int s = ed.x; float wt = __int_as_float(ed.y);
            float2 v0 = p0[(size_t)s * 32 + lane];
            float2 v1 = p1[(size_t)s * 32 + lane];
            a0.x = fmaf(wt, v0.x, a0.x); a0.y = fmaf(wt, v0.y, a0.y);
            a1.x = fmaf(wt, v1.x, a1.x); a1.y = fmaf(wt, v1.y, a1.y);
        }
    } else {
        for (int e = beg; e < end; e++) {
            int2 ed = g_csr[e];
            int s = ed.x; float wt = __int_as_float(ed.y);
            float2 v0 = p0[(size_t)s * 32 + lane];
            a0.x = fmaf(wt, v0.x, a0.x); a0.y = fmaf(wt, v0.y, a0.y);
        }
    }
    size_t o = (size_t)w * 32 + lane;
    if (sub0) { float2 sv = ((const float2*)sub0)[o]; a0.x = 2.f*a0.x - sv.x; a0.y = 2.f*a0.y - sv.y; }
    ((float2*)out0)[o] = a0;
    if (in1 && out1) {
        if (sub1) { float2 sv = ((const float2*)sub1)[o]; a1.x = 2.f*a1.x - sv.x; a1.y = 2.f*a1.y - sv.y; }
        ((float2*)out1)[o] = a1;
    }
}

// ---------------- fused GEMM (FFMA2 packed fp32) with GRU/MLP epilogues ----------------
// Tile: 256 rows x 64 cols, 256 threads. Per thread: 16 rows (8 f32x2 pairs) x 4 cols.
// Column mapping tx + 16*c  => B shared loads are 128B-contiguous per 16 lanes (bank-conflict-free).
struct GemmTerms { const float* t[6]; };

#define MODE_Z    0   // out = sigmoid(acc + b0 + b1)
#define MODE_RHR  1   // out = H * sigmoid(acc + b0 + b1)                (aux0 = H)
#define MODE_PRE  2   // out = acc + b0 + b1
#define MODE_G2   3   // Ht = tanh(acc + pre); H = relu(Z*H + (1-Z)*Ht)  (aux0=pre, aux1=Z, aux2=H)
#define MODE_RELU 4   // out = relu(acc + b0)

union U2 { unsigned long long u; float2 f; };

__global__ __launch_bounds__(256)
void k_gemm(GemmTerms A, const float* Acont, int lda,
            const float* B0, const float* B1, int ldb, int Ktot,
            const float* bias0, const float* bias1,
            float* out, int ldc, int mode,
            const float* aux0, const float* aux1, const float* aux2) {
    const int row0 = blockIdx.x * 256;
    const int col0 = blockIdx.y * 64;
    __shared__ __align__(16) float  As[16][256];   // A^T tile: As[k][r]
    __shared__ __align__(16) float2 Bs[16][64];    // B tile, value duplicated in both halves

    int tid = threadIdx.x;
    int tx = tid & 15;       // cols: tx, tx+16, tx+32, tx+48
    int ty = tid >> 4;       // rows: ty*16 .. ty*16+15 (8 packed pairs)

    U2 acc[8][4];
#pragma unroll
    for (int i = 0; i < 8; i++)
#pragma unroll
        for (int j = 0; j < 4; j++) acc[i][j].u = 0ull;

    for (int kb = 0; kb < Ktot; kb += 16) {
        // ---- A staging: each thread loads one row's 16 k-values, stores transposed
        {
            const float* ap;
            if (Acont) ap = Acont + (size_t)(row0 + tid) * lda + kb;
            else       ap = A.t[kb >> 6] + (size_t)(row0 + tid) * 64 + (kb & 63);
            float4 v0 = *(const float4*)(ap);
            float4 v1 = *(const float4*)(ap + 4);
            float4 v2 = *(const float4*)(ap + 8);
            float4 v3 = *(const float4*)(ap + 12);
            As[ 0][tid] = v0.x; As[ 1][tid] = v0.y; As[ 2][tid] = v0.z; As[ 3][tid] = v0.w;
            As[ 4][tid] = v1.x; As[ 5][tid] = v1.y; As[ 6][tid] = v1.z; As[ 7][tid] = v1.w;
            As[ 8][tid] = v2.x; As[ 9][tid] = v2.y; As[10][tid] = v2.z; As[11][tid] = v2.w;
            As[12][tid] = v3.x; As[13][tid] = v3.y; As[14][tid] = v3.z; As[15][tid] = v3.w;
        }
        // ---- B staging: 16 k-rows x 64 cols, duplicate each value into a float2
        {
            int kr = tid >> 4, cq = tid & 15;
            int krow = kb + kr;
            const float* brow = (B1 && krow >= 192) ? (B1 + (size_t)(krow - 192) * ldb)
                                                    : (B0 + (size_t)krow * ldb);
            float4 v = *(const float4*)(brow + col0 + cq * 4);
            Bs[kr][cq * 4 + 0] = make_float2(v.x, v.x);
            Bs[kr][cq * 4 + 1] = make_float2(v.y, v.y);
            Bs[kr][cq * 4 + 2] = make_float2(v.z, v.z);
            Bs[kr][cq * 4 + 3] = make_float2(v.w, v.w);
        }
        __syncthreads();
#pragma unroll
        for (int k = 0; k < 16; k++) {
            unsigned long long a[8], b[4];
#pragma unroll
            for (int q = 0; q < 4; q++) {
                ulonglong2 w = *(const ulonglong2*)&As[k][ty * 16 + 4 * q];
                a[2 * q]     = w.x;
                a[2 * q + 1] = w.y;
            }
#pragma unroll
            for (int c = 0; c < 4; c++)
                b[c] = *(const unsigned long long*)&Bs[k][tx + 16 * c];
#pragma unroll
            for (int p = 0; p < 8; p++)
#pragma unroll
                for (int c = 0; c < 4; c++)
                    asm("fma.rn.f32x2 %0, %1, %2, %0;"
                        : "+l"(acc[p][c].u) : "l"(a[p]), "l"(b[c]));
        }
        __syncthreads();
    }

    // ---- epilogue (accurate expf/tanhf — numerically identical to the R0-passing kernel)
#pragma unroll
    for (int c = 0; c < 4; c++) {
        int col = col0 + tx + 16 * c;
        float bb = 0.0f;
        if (bias0) bb += bias0[col];
        if (bias1) bb += bias1[col];
#pragma unroll
        for (int p = 0; p < 8; p++) {
            float2 v = acc[p][c].f;
#pragma unroll
            for (int h = 0; h < 2; h++) {
                int row = row0 + ty * 16 + 2 * p + h;
                float x = (h ? v.y : v.x) + bb;
                size_t oidx = (size_t)row * ldc + col;
                if (mode == MODE_Z) {
                    out[oidx] = fsigmoid(x);
                } else if (mode == MODE_RHR) {
                    out[oidx] = aux0[oidx] * fsigmoid(x);
                } else if (mode == MODE_PRE) {
                    out[oidx] = x;
                } else if (mode == MODE_G2) {
                    float ht = tanhf(x + aux0[oidx]);
                    float z  = aux1[oidx];
                    float h0 = aux2[oidx];
                    float hn = z * h0 + (1.0f - z) * ht;
                    out[oidx] = fmaxf(hn, 0.0f);
                } else { // MODE_RELU
                    out[oidx] = fmaxf(x, 0.0f);
                }
            }
        }
    }
}

// ---------------- head: logits (320 -> 2) + softmax, warp per row ----------------
__global__ void k_head(const float* __restrict__ y2, const float* __restrict__ W3,
                       const float* __restrict__ b3, float* __restrict__ out) {
    int w    = (blockIdx.x * blockDim.x + threadIdx.x) >> 5;
    int lane = threadIdx.x & 31;
    if (w >= BATCH) return;
    float p0 = 0.f, p1 = 0.f;
    for (int i = lane; i < MD3; i += 32) {
        float v = y2[(size_t)w * MD3 + i];
        p0 = fmaf(v, W3[i * 2 + 0], p0);
        p1 = fmaf(v, W3[i * 2 + 1], p1);
    }
#pragma unroll
    for (int o = 16; o; o >>= 1) {
        p0 += __shfl_xor_sync(0xffffffffu, p0, o);
        p1 += __shfl_xor_sync(0xffffffffu, p1, o);
    }
    if (lane == 0) {
        float l0 = p0 + b3[0], l1 = p1 + b3[1];
        float m = fmaxf(l0, l1);
        float e0 = expf(l0 - m), e1 = expf(l1 - m);
        float s = e0 + e1;
        out[(size_t)w * 2 + 0] = e0 / s;
        out[(size_t)w * 2 + 1] = e1 / s;
    }
}

// ---------------- host orchestration ----------------
extern "C" void kernel_launch(void* const* d_in, const int* in_sizes, int n_in,
                              void* d_out, int out_size) {
    const float* x_temporal = (const float*)d_in[0];
    const int*   edge_index = (const int*)d_in[1];
    const float* edge_w     = (const float*)d_in[2];
    const float* W_xz = (const float*)d_in[3];  const float* b_xz = (const float*)d_in[4];
    const float* W_hz = (const float*)d_in[5];  const float* b_hz = (const float*)d_in[6];
    const float* W_xr = (const float*)d_in[7];  const float* b_xr = (const float*)d_in[8];
    const float* W_hr = (const float*)d_in[9];  const float* b_hr = (const float*)d_in[10];
    const float* W_xh = (const float*)d_in[11]; const float* b_xh = (const float*)d_in[12];
    const float* W_hh = (const float*)d_in[13]; const float* b_hh = (const float*)d_in[14];
    const float* W1 = (const float*)d_in[15];   const float* b1 = (const float*)d_in[16];
    const float* W2 = (const float*)d_in[17];   const float* b2 = (const float*)d_in[18];
    const float* W3 = (const float*)d_in[19];   const float* b3 = (const float*)d_in[20];
    float* out = (float*)d_out;

    float *T1x, *T2x, *T1h, *T2h, *H, *Z, *HR, *PRE, *y1, *y2;
    cudaGetSymbolAddress((void**)&T1x, g_T1x);
    cudaGetSymbolAddress((void**)&T2x, g_T2x);
    cudaGetSymbolAddress((void**)&T1h, g_T1h);
    cudaGetSymbolAddress((void**)&T2h, g_T2h);
    cudaGetSymbolAddress((void**)&H,   g_Hst);
    cudaGetSymbolAddress((void**)&Z,   g_Zg);
    cudaGetSymbolAddress((void**)&HR,  g_HR);
    cudaGetSymbolAddress((void**)&PRE, g_pre);
    cudaGetSymbolAddress((void**)&y1,  g_y1);
    cudaGetSymbolAddress((void**)&y2,  g_y2);

    // graph preprocessing (every call: deterministic, replay-safe)
    k_init  <<<(BN * FDIM) / 256, 256>>>();
    k_degcnt<<<NE / 256, 256>>>(edge_index, edge_w);
    k_dinv  <<<BN / 256, 256>>>();
    k_scan1 <<<80, 1024>>>();
    k_scan2 <<<1, 128>>>();
    k_scan3 <<<80, 1024>>>();
    k_fill  <<<NE / 256, 256>>>(edge_index, edge_w);

    const int spmm_blocks = BN / 8;  // warp per row, 8 warps per block
    const int gemm_blocks = BN / 256;

    for (int t = 0; t < T_STEPS; t++) {
        const float* X = x_temporal + (size_t)t * BN * FDIM;

        // Chebyshev terms for X and H branches
        k_spmm<<<spmm_blocks, 256>>>(X,   H,   T1x, T1h, nullptr, nullptr);
        k_spmm<<<spmm_blocks, 256>>>(T1x, T1h, T2x, T2h, X, H);

        GemmTerms A6; A6.t[0] = X; A6.t[1] = T1x; A6.t[2] = T2x;
                      A6.t[3] = H; A6.t[4] = T1h; A6.t[5] = T2h;
        // Z gate
        k_gemm<<<dim3(gemm_blocks, 1), 256>>>(A6, nullptr, 0, W_xz, W_hz, 64, 384,
                                              b_xz, b_hz, Z, 64, MODE_Z,
                                              nullptr, nullptr, nullptr);
        // R gate fused with HR = H * R
        k_gemm<<<dim3(gemm_blocks, 1), 256>>>(A6, nullptr, 0, W_xr, W_hr, 64, 384,
                                              b_xr, b_hr, HR, 64, MODE_RHR,
                                              H, nullptr, nullptr);
        // candidate X-branch pre-activation (+ both candidate biases)
        GemmTerms A3; A3.t[0] = X; A3.t[1] = T1x; A3.t[2] = T2x;
                      A3.t[3] = nullptr; A3.t[4] = nullptr; A3.t[5] = nullptr;
        k_gemm<<<dim3(gemm_blocks, 1), 256>>>(A3, nullptr, 0, W_xh, nullptr, 64, 192,
                                              b_xh, b_hh, PRE, 64, MODE_PRE,
                                              nullptr, nullptr, nullptr);

        // Chebyshev terms for HR branch (reuse T1x/T2x buffers)
        k_spmm<<<spmm_blocks, 256>>>(HR,  nullptr, T1x, nullptr, nullptr, nullptr);
        k_spmm<<<spmm_blocks, 256>>>(T1x, nullptr, T2x, nullptr, HR, nullptr);

        // candidate H-branch GEMM fused with full GRU update (writes H in place)
        GemmTerms A3r; A3r.t[0] = HR; A3r.t[1] = T1x; A3r.t[2] = T2x;
                       A3r.t[3] = nullptr; A3r.t[4] = nullptr; A3r.t[5] = nullptr;
        k_gemm<<<dim3(gemm_blocks, 1), 256>>>(A3r, nullptr, 0, W_hh, nullptr, 64, 192,
                                              nullptr, nullptr, H, 64, MODE_G2,
                                              PRE, Z, H);
    }

    // MLP head: H viewed as [4096 x 1280]
    GemmTerms dummy; for (int i = 0; i < 6; i++) dummy.t[i] = nullptr;
    k_gemm<<<dim3(BATCH / 256, MD2 / 64), 256>>>(dummy, H, MD1, W1, nullptr, MD2, MD1,
                                                 b1, nullptr, y1, MD2, MODE_RELU,
                                                 nullptr, nullptr, nullptr);
    k_gemm<<<dim3(BATCH / 256, MD3 / 64), 256>>>(dummy, y1, MD2, W2, nullptr, MD3, MD2,
                                                 b2, nullptr, y2, MD3, MODE_RELU,
                                                 nullptr, nullptr, nullptr);
    k_head<<<BATCH / 8, 256>>>(y2, W3, b3, out);
}